// round 11
// baseline (speedup 1.0000x reference)
#include <cuda_runtime.h>
#include <math.h>
#include <stdint.h>

// Problem constants: B=2, T=2048, C=1024, H=16, hd=64
constexpr int kT  = 2048;
constexpr int kC  = 1024;
constexpr int kH  = 16;
constexpr int kHD = 64;
constexpr int kB  = 2;

// Scratch (allocation-free rule: __device__ globals)
__device__ float g_q[kB * kH * kT * kHD];     // Q in [B,H,T,hd]        (16 MB)
__device__ float g_yatt[kB * kT * kC];        // attn out (tf32-rounded) (16 MB)
__device__ float g_xc[kB * kT * kC];          // x, tf32-rounded         (16 MB)
__device__ float g_wc[kC * 3 * kC];           // W_attn, tf32-rounded    (12 MB)
__device__ float g_wp[kC * kC];               // W_proj, tf32-rounded    ( 4 MB)

// ---------------------------------------------------------------------------
// TF32 + cp.async helpers
// ---------------------------------------------------------------------------
__device__ __forceinline__ float to_tf32(float x) {
    float r;
    asm("cvt.rna.tf32.f32 %0, %1;" : "=f"(r) : "f"(x));
    return r;
}

__device__ __forceinline__ void mma_tf32(float* c, const uint32_t* a, const uint32_t* b) {
    asm volatile(
        "mma.sync.aligned.m16n8k8.row.col.f32.tf32.tf32.f32 "
        "{%0,%1,%2,%3}, {%4,%5,%6,%7}, {%8,%9}, {%0,%1,%2,%3};\n"
        : "+f"(c[0]), "+f"(c[1]), "+f"(c[2]), "+f"(c[3])
        : "r"(a[0]), "r"(a[1]), "r"(a[2]), "r"(a[3]), "r"(b[0]), "r"(b[1]));
}

__device__ __forceinline__ uint32_t smem_u32(const void* p) {
    uint32_t a;
    asm("{ .reg .u64 t; cvta.to.shared.u64 t, %1; cvt.u32.u64 %0, t; }"
        : "=r"(a) : "l"(p));
    return a;
}

#define CP_ASYNC16(saddr, gptr) \
    asm volatile("cp.async.cg.shared.global [%0], [%1], 16;" \
                 :: "r"(saddr), "l"(gptr) : "memory")
#define CP_COMMIT() asm volatile("cp.async.commit_group;" ::: "memory")
#define CP_WAIT1()  asm volatile("cp.async.wait_group 1;" ::: "memory")
#define CP_WAIT0()  asm volatile("cp.async.wait_group 0;" ::: "memory")

// ---------------------------------------------------------------------------
// Pre-round inputs to tf32 (single RNA rounding; hot loops stay cvt-free).
// ---------------------------------------------------------------------------
constexpr int kX4  = kB * kT * kC / 4;        // 1048576
constexpr int kWA4 = kC * 3 * kC / 4;         //  786432
constexpr int kWP4 = kC * kC / 4;             //  262144
constexpr int kCvtTotal4 = kX4 + kWA4 + kWP4; // 2097152

__global__ void __launch_bounds__(256) cvt_tf32_kernel(
    const float* __restrict__ x, const float* __restrict__ wa,
    const float* __restrict__ wp)
{
    int i = blockIdx.x * blockDim.x + threadIdx.x;
    const float4* src;
    float4* dst;
    if (i < kX4) {
        src = reinterpret_cast<const float4*>(x) + i;
        dst = reinterpret_cast<float4*>(g_xc) + i;
    } else if (i < kX4 + kWA4) {
        src = reinterpret_cast<const float4*>(wa) + (i - kX4);
        dst = reinterpret_cast<float4*>(g_wc) + (i - kX4);
    } else {
        src = reinterpret_cast<const float4*>(wp) + (i - kX4 - kWA4);
        dst = reinterpret_cast<float4*>(g_wp) + (i - kX4 - kWA4);
    }
    float4 v = *src;
    float4 o = {to_tf32(v.x), to_tf32(v.y), to_tf32(v.z), to_tf32(v.w)};
    *dst = o;
}

// ---------------------------------------------------------------------------
// TF32 MMA GEMM v4. CTA 128x128, BK=16, 256 threads (8 warps: 2m x 4n),
// warp tile 64x32. 3-stage cp.async pipeline, ONE __syncthreads per slab
// (prefetch target (s+2)%3 is untouched by current readers).
//   As[3][128][20]  (stride 20: 20*gid mod 32 bijective => frag reads CF)
//   Bs[3][16][136]  (stride 136: frag bank = 8*tig+gid bijective, CF)
// Inputs must already be tf32-rounded (g_xc/g_wc/g_wp/g_yatt).
// ---------------------------------------------------------------------------
constexpr int kAStrideF = 20;   // floats; 80 B/row (16 k + 4 pad)
constexpr int kBStrideF = 136;  // floats; 544 B/row
constexpr int kABufF = 128 * kAStrideF;   // 2560 floats = 10240 B
constexpr int kBBufF = 16 * kBStrideF;    // 2176 floats =  8704 B
constexpr int kGemmSmemBytes = 3 * (kABufF + kBBufF) * 4;  // 56832

template <int N_, typename Epilogue>
__device__ __forceinline__ void gemm_tf32_core(
    const float* __restrict__ A, const float* __restrict__ W,
    Epilogue epi)
{
    constexpr int K = kC;            // 1024
    constexpr int NSLAB = K / 16;    // 64
    extern __shared__ float smf[];
    float* As = smf;                    // [3][2560]
    float* Bs = smf + 3 * kABufF;       // [3][2176]

    const int m0 = blockIdx.y * 128;
    const int n0 = blockIdx.x * 128;
    const int tid  = threadIdx.x;
    const int lane = tid & 31;
    const int wid  = tid >> 5;
    const int wm = wid >> 2;      // 0..1
    const int wn = wid & 3;       // 0..3
    const int gid = lane >> 2, tig = lane & 3;

    const uint32_t aBase = smem_u32(As);
    const uint32_t bBase = smem_u32(Bs);

    // ---- per-thread staging constants (2 x 16B chunks each for A and B) ----
    // A: row = it*64 + (tid>>2), chunk = tid&3  (4 chunks of 16B per row)
    const int aRow = tid >> 2;
    const int aC16 = tid & 3;
    const float* aG[2];
    uint32_t aS[2];
#pragma unroll
    for (int it = 0; it < 2; it++) {
        aG[it] = A + (size_t)(m0 + it * 64 + aRow) * K + aC16 * 4;
        aS[it] = (uint32_t)((it * 64 + aRow) * 80 + aC16 * 16);
    }
    // B: k-row = it*8 + (tid>>5), chunk = tid&31
    const int bRow = tid >> 5;
    const int bC16 = tid & 31;
    const float* bG[2];
    uint32_t bS[2];
#pragma unroll
    for (int it = 0; it < 2; it++) {
        bG[it] = W + (size_t)(it * 8 + bRow) * N_ + n0 + bC16 * 4;
        bS[it] = (uint32_t)((it * 8 + bRow) * 544 + bC16 * 16);
    }

    auto issue = [&](int s, int buf) {
        const int k0 = s * 16;
        uint32_t ab = aBase + buf * (kABufF * 4);
        uint32_t bb = bBase + buf * (kBBufF * 4);
#pragma unroll
        for (int it = 0; it < 2; it++)
            CP_ASYNC16(ab + aS[it], aG[it] + k0);
        size_t wof = (size_t)k0 * N_;
#pragma unroll
        for (int it = 0; it < 2; it++)
            CP_ASYNC16(bb + bS[it], bG[it] + wof);
        CP_COMMIT();
    };

    float acc[4][4][4];
#pragma unroll
    for (int i = 0; i < 4; i++)
#pragma unroll
        for (int j = 0; j < 4; j++)
#pragma unroll
            for (int c = 0; c < 4; c++) acc[i][j][c] = 0.f;

    issue(0, 0);
    issue(1, 1);

    const int arow0 = wm * 64 + gid;
    const int nb0   = wn * 32 + gid;

    int bufR = 0;          // s % 3
    int bufW = 2;          // (s+2) % 3
    for (int s = 0; s < NSLAB; s++) {
        if (s >= NSLAB - 2) { CP_WAIT0(); } else { CP_WAIT1(); }
        __syncthreads();
        if (s + 2 < NSLAB) issue(s + 2, bufW);

        const float* ab = As + bufR * kABufF;
        const float* bb = Bs + bufR * kBBufF;
#pragma unroll
        for (int kc = 0; kc < 2; kc++) {
            const int kcol = kc * 8 + tig;
            uint32_t a[4][4], b[4][2];
#pragma unroll
            for (int mt = 0; mt < 4; mt++) {
                const float* p = ab + (arow0 + mt * 16) * kAStrideF + kcol;
                a[mt][0] = __float_as_uint(p[0]);
                a[mt][1] = __float_as_uint(p[8 * kAStrideF]);
                a[mt][2] = __float_as_uint(p[4]);
                a[mt][3] = __float_as_uint(p[8 * kAStrideF + 4]);
            }
#pragma unroll
            for (int nt = 0; nt < 4; nt++) {
                const float* q = bb + kcol * kBStrideF + nb0 + nt * 8;
                b[nt][0] = __float_as_uint(q[0]);
                b[nt][1] = __float_as_uint(q[4 * kBStrideF]);
            }
#pragma unroll
            for (int mt = 0; mt < 4; mt++)
#pragma unroll
                for (int nt = 0; nt < 4; nt++)
                    mma_tf32(acc[mt][nt], a[mt], b[nt]);
        }
        bufR = (bufR == 2) ? 0 : bufR + 1;
        bufW = (bufW == 2) ? 0 : bufW + 1;
    }

    // ---- epilogue ----
#pragma unroll
    for (int mt = 0; mt < 4; mt++)
#pragma unroll
        for (int nt = 0; nt < 4; nt++)
#pragma unroll
            for (int c = 0; c < 4; c++) {
                int m = m0 + wm * 64 + mt * 16 + gid + 8 * (c >> 1);
                int n = n0 + wn * 32 + nt * 8 + tig * 2 + (c & 1);
                epi(m, n, acc[mt][nt][c]);
            }
}

struct QkvEpilogue {
    const float* bias;
    float* kout;
    float* vout;
    __device__ __forceinline__ void operator()(int m, int n, float v) const {
        v += bias[n];
        int bidx = m >> 11;
        int t    = m & 2047;
        int s = n >> 10;
        int cc = n & 1023;
        int h = cc >> 6, d = cc & 63;
        int idx = ((bidx * kH + h) * kT + t) * kHD + d;
        if (s == 0)      g_q[idx]  = v;
        else if (s == 1) kout[idx] = v;
        else             vout[idx] = v;
    }
};

__global__ void __launch_bounds__(256, 2) qkv_gemm_kernel(
    const float* __restrict__ bias,
    float* __restrict__ kout, float* __restrict__ vout)
{
    QkvEpilogue epi{bias, kout, vout};
    gemm_tf32_core<3 * kC>(g_xc, g_wc, epi);
}

struct ProjEpilogue {
    const float* bias;
    float* out;
    __device__ __forceinline__ void operator()(int m, int n, float v) const {
        out[(size_t)m * kC + n] = v + bias[n];
    }
};

__global__ void __launch_bounds__(256, 2) proj_gemm_kernel(
    const float* __restrict__ bias, float* __restrict__ out)
{
    ProjEpilogue epi{bias, out};
    gemm_tf32_core<kC>(g_yatt, g_wp, epi);
}

// ---------------------------------------------------------------------------
// TF32 MMA flash attention (R3 core). BR=BC=64, 128 threads = 4 warps.
// qi reversed so heaviest CTAs launch first (tail reduction).
// ---------------------------------------------------------------------------
constexpr int kFlashSmemBytes = 3 * 64 * 68 * 4;

__global__ void __launch_bounds__(128) flash_kernel(
    const float* __restrict__ Kg, const float* __restrict__ Vg)
{
    extern __shared__ float sm[];
    float* Ks = sm;               // [64][68]
    float* Vt = sm + 64 * 68;     // [64][68]  (Vt[d][c])
    float* Ss = sm + 2 * 64 * 68; // [64][68]

    const int tid  = threadIdx.x;
    const int lane = tid & 31;
    const int wid  = tid >> 5;
    const int gid  = lane >> 2;
    const int tig  = lane & 3;
    const int qi = (gridDim.x - 1) - blockIdx.x;   // heavy CTAs first
    const int h = blockIdx.y, b = blockIdx.z;
    const int qbase = qi * 64;
    const int r0 = wid * 16;

    const size_t head_off = (size_t)(b * kH + h) * kT * kHD;
    const float* Qp = g_q + head_off;
    const float* Kp = Kg + head_off;
    const float* Vp = Vg + head_off;

#pragma unroll
    for (int it = 0; it < 8; it++) {
        int f = it * 128 + tid;
        int r = f >> 4, dq = (f & 15) * 4;
        float4 q4 = *reinterpret_cast<const float4*>(Qp + (size_t)(qbase + r) * kHD + dq);
        float* d = Ss + r * 68 + dq;
        d[0] = q4.x; d[1] = q4.y; d[2] = q4.z; d[3] = q4.w;
    }
    __syncthreads();

    uint32_t qf[8][4];
#pragma unroll
    for (int kc = 0; kc < 8; kc++) {
        const float* base = Ss + (r0 + gid) * 68 + kc * 8 + tig;
        qf[kc][0] = __float_as_uint(to_tf32(0.125f * base[0]));
        qf[kc][1] = __float_as_uint(to_tf32(0.125f * base[8 * 68]));
        qf[kc][2] = __float_as_uint(to_tf32(0.125f * base[4]));
        qf[kc][3] = __float_as_uint(to_tf32(0.125f * base[8 * 68 + 4]));
    }

    float mA = -INFINITY, mB = -INFINITY, lA = 0.f, lB = 0.f;
    float oacc[8][4];
#pragma unroll
    for (int nt = 0; nt < 8; nt++)
#pragma unroll
        for (int c = 0; c < 4; c++) oacc[nt][c] = 0.f;

    const int ntiles = qi + 1;
    const int vdpb = tid & 15, vcb4 = tid >> 4;

    for (int jt = 0; jt < ntiles; jt++) {
        __syncthreads();
#pragma unroll
        for (int it = 0; it < 8; it++) {
            int f = it * 128 + tid;
            int r = f >> 4, dq = (f & 15) * 4;
            float4 k4 = *reinterpret_cast<const float4*>(Kp + (size_t)(jt * 64 + r) * kHD + dq);
            float* d = Ks + r * 68 + dq;
            d[0] = to_tf32(k4.x); d[1] = to_tf32(k4.y);
            d[2] = to_tf32(k4.z); d[3] = to_tf32(k4.w);
        }
#pragma unroll
        for (int it = 0; it < 2; it++) {
            int cb = vcb4 + 8 * it;
            const float* vsrc = Vp + (size_t)(jt * 64 + cb * 4) * kHD + vdpb * 4;
            float4 a0 = *reinterpret_cast<const float4*>(vsrc);
            float4 a1 = *reinterpret_cast<const float4*>(vsrc + kHD);
            float4 a2 = *reinterpret_cast<const float4*>(vsrc + 2 * kHD);
            float4 a3 = *reinterpret_cast<const float4*>(vsrc + 3 * kHD);
            float4 t0 = {to_tf32(a0.x), to_tf32(a1.x), to_tf32(a2.x), to_tf32(a3.x)};
            float4 t1 = {to_tf32(a0.y), to_tf32(a1.y), to_tf32(a2.y), to_tf32(a3.y)};
            float4 t2 = {to_tf32(a0.z), to_tf32(a1.z), to_tf32(a2.z), to_tf32(a3.z)};
            float4 t3 = {to_tf32(a0.w), to_tf32(a1.w), to_tf32(a2.w), to_tf32(a3.w)};
            *reinterpret_cast<float4*>(Vt + (vdpb * 4 + 0) * 68 + cb * 4) = t0;
            *reinterpret_cast<float4*>(Vt + (vdpb * 4 + 1) * 68 + cb * 4) = t1;
            *reinterpret_cast<float4*>(Vt + (vdpb * 4 + 2) * 68 + cb * 4) = t2;
            *reinterpret_cast<float4*>(Vt + (vdpb * 4 + 3) * 68 + cb * 4) = t3;
        }
        __syncthreads();

        float sa[8][4];
#pragma unroll
        for (int nt = 0; nt < 8; nt++)
#pragma unroll
            for (int c = 0; c < 4; c++) sa[nt][c] = 0.f;
#pragma unroll
        for (int kc = 0; kc < 8; kc++) {
#pragma unroll
            for (int nt = 0; nt < 8; nt++) {
                const float* bp = Ks + (nt * 8 + gid) * 68 + kc * 8 + tig;
                uint32_t bb[2];
                bb[0] = __float_as_uint(bp[0]);
                bb[1] = __float_as_uint(bp[4]);
                mma_tf32(sa[nt], qf[kc], bb);
            }
        }

        if (jt == ntiles - 1) {
            int rowA = r0 + gid, rowB = rowA + 8;
#pragma unroll
            for (int nt = 0; nt < 8; nt++) {
                int c0 = nt * 8 + tig * 2, c1 = c0 + 1;
                if (c0 > rowA) sa[nt][0] = -INFINITY;
                if (c1 > rowA) sa[nt][1] = -INFINITY;
                if (c0 > rowB) sa[nt][2] = -INFINITY;
                if (c1 > rowB) sa[nt][3] = -INFINITY;
            }
        }

        float mxA = -INFINITY, mxB = -INFINITY;
#pragma unroll
        for (int nt = 0; nt < 8; nt++) {
            mxA = fmaxf(mxA, fmaxf(sa[nt][0], sa[nt][1]));
            mxB = fmaxf(mxB, fmaxf(sa[nt][2], sa[nt][3]));
        }
        mxA = fmaxf(mxA, __shfl_xor_sync(0xffffffff, mxA, 1));
        mxA = fmaxf(mxA, __shfl_xor_sync(0xffffffff, mxA, 2));
        mxB = fmaxf(mxB, __shfl_xor_sync(0xffffffff, mxB, 1));
        mxB = fmaxf(mxB, __shfl_xor_sync(0xffffffff, mxB, 2));

        float mnA = fmaxf(mA, mxA), mnB = fmaxf(mB, mxB);
        float alphaA = __expf(mA - mnA), alphaB = __expf(mB - mnB);

        float sumA = 0.f, sumB = 0.f;
        float* prowA = Ss + (r0 + gid) * 68 + tig * 2;
        float* prowB = prowA + 8 * 68;
#pragma unroll
        for (int nt = 0; nt < 8; nt++) {
            float p0 = __expf(sa[nt][0] - mnA);
            float p1 = __expf(sa[nt][1] - mnA);
            float p2 = __expf(sa[nt][2] - mnB);
            float p3 = __expf(sa[nt][3] - mnB);
            float q0 = to_tf32(p0), q1 = to_tf32(p1);
            float q2 = to_tf32(p2), q3 = to_tf32(p3);
            sumA += q0 + q1;
            sumB += q2 + q3;
            prowA[nt * 8 + 0] = q0; prowA[nt * 8 + 1] = q1;
            prowB[nt * 8 + 0] = q2; prowB[nt * 8 + 1] = q3;
        }
        sumA += __shfl_xor_sync(0xffffffff, sumA, 1);
        sumA += __shfl_xor_sync(0xffffffff, sumA, 2);
        sumB += __shfl_xor_sync(0xffffffff, sumB, 1);
        sumB += __shfl_xor_sync(0xffffffff, sumB, 2);

        lA = lA * alphaA + sumA;  mA = mnA;
        lB = lB * alphaB + sumB;  mB = mnB;

#pragma unroll
        for (int nt = 0; nt < 8; nt++) {
            oacc[nt][0] *= alphaA; oacc[nt][1] *= alphaA;
            oacc[nt][2] *= alphaB; oacc[nt][3] *= alphaB;
        }
        __syncwarp();

#pragma unroll
        for (int kc = 0; kc < 8; kc++) {
            const float* ap = Ss + (r0 + gid) * 68 + kc * 8 + tig;
            uint32_t pa[4];
            pa[0] = __float_as_uint(ap[0]);
            pa[1] = __float_as_uint(ap[8 * 68]);
            pa[2] = __float_as_uint(ap[4]);
            pa[3] = __float_as_uint(ap[8 * 68 + 4]);
#pragma unroll
            for (int nt = 0; nt < 8; nt++) {
                const float* bp = Vt + (nt * 8 + gid) * 68 + kc * 8 + tig;
                uint32_t bb[2];
                bb[0] = __float_as_uint(bp[0]);
                bb[1] = __float_as_uint(bp[4]);
                mma_tf32(oacc[nt], pa, bb);
            }
        }
        __syncwarp();
    }

    // Output is tf32-rounded so proj can consume it without converting.
    float ilA = 1.f / lA, ilB = 1.f / lB;
    float* ypA = g_yatt + ((size_t)(b * kT + qbase + r0 + gid)) * kC + h * kHD;
    float* ypB = ypA + (size_t)8 * kC;
#pragma unroll
    for (int nt = 0; nt < 8; nt++) {
        float2 vA = {to_tf32(oacc[nt][0] * ilA), to_tf32(oacc[nt][1] * ilA)};
        float2 vB = {to_tf32(oacc[nt][2] * ilB), to_tf32(oacc[nt][3] * ilB)};
        *reinterpret_cast<float2*>(ypA + nt * 8 + tig * 2) = vA;
        *reinterpret_cast<float2*>(ypB + nt * 8 + tig * 2) = vB;
    }
}

// ---------------------------------------------------------------------------
// Launch: cvt -> qkv -> flash -> proj, sequential default stream (capturable).
// Output layout: [ y (B*T*C) | k (B*H*T*hd) | v (B*H*T*hd) ]
// ---------------------------------------------------------------------------
extern "C" void kernel_launch(void* const* d_in, const int* in_sizes, int n_in,
                              void* d_out, int out_size)
{
    const float* x      = (const float*)d_in[0];
    const float* W_attn = (const float*)d_in[1];
    const float* b_attn = (const float*)d_in[2];
    const float* W_proj = (const float*)d_in[3];
    const float* b_proj = (const float*)d_in[4];

    float* y = (float*)d_out;
    const int seg = out_size / 3;       // 4,194,304 each
    float* kout = y + seg;
    float* vout = y + 2 * seg;

    cudaFuncSetAttribute(qkv_gemm_kernel,
                         cudaFuncAttributeMaxDynamicSharedMemorySize, kGemmSmemBytes);
    cudaFuncSetAttribute(proj_gemm_kernel,
                         cudaFuncAttributeMaxDynamicSharedMemorySize, kGemmSmemBytes);
    cudaFuncSetAttribute(flash_kernel,
                         cudaFuncAttributeMaxDynamicSharedMemorySize, kFlashSmemBytes);

    cvt_tf32_kernel<<<kCvtTotal4 / 256, 256>>>(x, W_attn, W_proj);
    // QKV: M=4096 -> 32 m-tiles, N=3072 -> 24 n-tiles
    qkv_gemm_kernel<<<dim3(24, 32), 256, kGemmSmemBytes>>>(b_attn, kout, vout);
    // Attention: (T/64, H, B)
    flash_kernel<<<dim3(32, 16, 2), 128, kFlashSmemBytes>>>(kout, vout);
    // Proj: N=1024 -> 8 n-tiles
    proj_gemm_kernel<<<dim3(8, 32), 256, kGemmSmemBytes>>>(b_proj, y);
}

// round 13
// speedup vs baseline: 1.0152x; 1.0152x over previous
#include <cuda_runtime.h>
#include <math.h>
#include <stdint.h>

// Problem constants: B=2, T=2048, C=1024, H=16, hd=64
constexpr int kT  = 2048;
constexpr int kC  = 1024;
constexpr int kH  = 16;
constexpr int kHD = 64;
constexpr int kB  = 2;

// Scratch (allocation-free rule: __device__ globals)
__device__ float g_q[kB * kH * kT * kHD];     // Q in [B,H,T,hd]        (16 MB)
__device__ float g_yatt[kB * kT * kC];        // attn out (tf32-rounded) (16 MB)
__device__ float g_xc[kB * kT * kC];          // x, tf32-rounded         (16 MB)
__device__ float g_wc[kC * 3 * kC];           // W_attn, tf32-rounded    (12 MB)
__device__ float g_wp[kC * kC];               // W_proj, tf32-rounded    ( 4 MB)

// ---------------------------------------------------------------------------
// TF32 + cp.async helpers
// ---------------------------------------------------------------------------
__device__ __forceinline__ float to_tf32(float x) {
    float r;
    asm("cvt.rna.tf32.f32 %0, %1;" : "=f"(r) : "f"(x));
    return r;
}

__device__ __forceinline__ void mma_tf32(float* c, const uint32_t* a, const uint32_t* b) {
    asm volatile(
        "mma.sync.aligned.m16n8k8.row.col.f32.tf32.tf32.f32 "
        "{%0,%1,%2,%3}, {%4,%5,%6,%7}, {%8,%9}, {%0,%1,%2,%3};\n"
        : "+f"(c[0]), "+f"(c[1]), "+f"(c[2]), "+f"(c[3])
        : "r"(a[0]), "r"(a[1]), "r"(a[2]), "r"(a[3]), "r"(b[0]), "r"(b[1]));
}

__device__ __forceinline__ uint32_t smem_u32(const void* p) {
    uint32_t a;
    asm("{ .reg .u64 t; cvta.to.shared.u64 t, %1; cvt.u32.u64 %0, t; }"
        : "=r"(a) : "l"(p));
    return a;
}

#define CP_ASYNC16(saddr, gptr) \
    asm volatile("cp.async.cg.shared.global [%0], [%1], 16;" \
                 :: "r"(saddr), "l"(gptr) : "memory")
#define CP_COMMIT() asm volatile("cp.async.commit_group;" ::: "memory")
#define CP_WAIT1()  asm volatile("cp.async.wait_group 1;" ::: "memory")
#define CP_WAIT0()  asm volatile("cp.async.wait_group 0;" ::: "memory")

// ---------------------------------------------------------------------------
// Pre-round inputs to tf32 (single RNA rounding; hot loops stay cvt-free).
// ---------------------------------------------------------------------------
constexpr int kX4  = kB * kT * kC / 4;        // 1048576
constexpr int kWA4 = kC * 3 * kC / 4;         //  786432
constexpr int kWP4 = kC * kC / 4;             //  262144
constexpr int kCvtTotal4 = kX4 + kWA4 + kWP4; // 2097152

__global__ void __launch_bounds__(256) cvt_tf32_kernel(
    const float* __restrict__ x, const float* __restrict__ wa,
    const float* __restrict__ wp)
{
    int i = blockIdx.x * blockDim.x + threadIdx.x;
    const float4* src;
    float4* dst;
    if (i < kX4) {
        src = reinterpret_cast<const float4*>(x) + i;
        dst = reinterpret_cast<float4*>(g_xc) + i;
    } else if (i < kX4 + kWA4) {
        src = reinterpret_cast<const float4*>(wa) + (i - kX4);
        dst = reinterpret_cast<float4*>(g_wc) + (i - kX4);
    } else {
        src = reinterpret_cast<const float4*>(wp) + (i - kX4 - kWA4);
        dst = reinterpret_cast<float4*>(g_wp) + (i - kX4 - kWA4);
    }
    float4 v = *src;
    float4 o = {to_tf32(v.x), to_tf32(v.y), to_tf32(v.z), to_tf32(v.w)};
    *dst = o;
}

// ---------------------------------------------------------------------------
// TF32 MMA GEMM (R10 config — measured best). CTA 128x128, BK=32, 256 threads
// (8 warps: 2m x 4n), warp tile 64x32. cp.async double-buffered staging:
//   As[2][128][36]  (stride 36: frag bank = 4*gid+tig = lane, conflict-free)
//   Bs[2][32][136]  (stride 136: frag bank = 8*tig+gid, bijective, CF)
// Inputs must already be tf32-rounded (g_xc/g_wc/g_wp/g_yatt).
// ---------------------------------------------------------------------------
constexpr int kAStrideF = 36;   // floats; 144 B/row
constexpr int kBStrideF = 136;  // floats; 544 B/row
constexpr int kABufF = 128 * kAStrideF;   // 4608 floats = 18432 B
constexpr int kBBufF = 32 * kBStrideF;    // 4352 floats = 17408 B
constexpr int kGemmSmemBytes = (2 * kABufF + 2 * kBBufF) * 4;  // 71680

template <int N_, typename Epilogue>
__device__ __forceinline__ void gemm_tf32_core(
    const float* __restrict__ A, const float* __restrict__ W,
    Epilogue epi)
{
    constexpr int K = kC;  // 1024
    extern __shared__ float smf[];
    float* As = smf;                    // [2][4608]
    float* Bs = smf + 2 * kABufF;       // [2][4352]

    const int m0 = blockIdx.y * 128;
    const int n0 = blockIdx.x * 128;
    const int tid  = threadIdx.x;
    const int lane = tid & 31;
    const int wid  = tid >> 5;
    const int wm = wid >> 2;      // 0..1
    const int wn = wid & 3;       // 0..3
    const int gid = lane >> 2, tig = lane & 3;

    const uint32_t aBase = smem_u32(As);
    const uint32_t bBase = smem_u32(Bs);

    // A: 4 chunks of 16B: row = it*32 + (tid>>3), k-chunk = (tid&7)
    const int aRow = tid >> 3;
    const int aC16 = tid & 7;
    const float* aG[4];
    uint32_t aS[4];
#pragma unroll
    for (int it = 0; it < 4; it++) {
        aG[it] = A + (size_t)(m0 + it * 32 + aRow) * K + aC16 * 4;
        aS[it] = (uint32_t)((it * 32 + aRow) * 144 + aC16 * 16);
    }
    // B: 4 chunks: k-row = it*8 + (tid>>5), n-chunk = (tid&31)
    const int bRow = tid >> 5;
    const int bC16 = tid & 31;
    const float* bG[4];
    uint32_t bS[4];
#pragma unroll
    for (int it = 0; it < 4; it++) {
        bG[it] = W + (size_t)(it * 8 + bRow) * N_ + n0 + bC16 * 4;
        bS[it] = (uint32_t)((it * 8 + bRow) * 544 + bC16 * 16);
    }

    auto issue = [&](int k0, int buf) {
        uint32_t ab = aBase + buf * (kABufF * 4);
        uint32_t bb = bBase + buf * (kBBufF * 4);
#pragma unroll
        for (int it = 0; it < 4; it++)
            CP_ASYNC16(ab + aS[it], aG[it] + k0);
        size_t wof = (size_t)k0 * N_;
#pragma unroll
        for (int it = 0; it < 4; it++)
            CP_ASYNC16(bb + bS[it], bG[it] + wof);
        CP_COMMIT();
    };

    float acc[4][4][4];
#pragma unroll
    for (int i = 0; i < 4; i++)
#pragma unroll
        for (int j = 0; j < 4; j++)
#pragma unroll
            for (int c = 0; c < 4; c++) acc[i][j][c] = 0.f;

    issue(0, 0);
    issue(32, 1);

    const int arow0 = wm * 64 + gid;
    const int nb0   = wn * 32 + gid;

    for (int s = 0; s < K / 32; s++) {
        if (s < K / 32 - 1) CP_WAIT1(); else CP_WAIT0();
        __syncthreads();

        const float* ab = As + (s & 1) * kABufF;
        const float* bb = Bs + (s & 1) * kBBufF;
#pragma unroll
        for (int kc = 0; kc < 4; kc++) {
            const int kcol = kc * 8 + tig;
            uint32_t a[4][4], b[4][2];
#pragma unroll
            for (int mt = 0; mt < 4; mt++) {
                const float* p = ab + (arow0 + mt * 16) * kAStrideF + kcol;
                a[mt][0] = __float_as_uint(p[0]);
                a[mt][1] = __float_as_uint(p[8 * kAStrideF]);
                a[mt][2] = __float_as_uint(p[4]);
                a[mt][3] = __float_as_uint(p[8 * kAStrideF + 4]);
            }
#pragma unroll
            for (int nt = 0; nt < 4; nt++) {
                const float* q = bb + kcol * kBStrideF + nb0 + nt * 8;
                b[nt][0] = __float_as_uint(q[0]);
                b[nt][1] = __float_as_uint(q[4 * kBStrideF]);
            }
#pragma unroll
            for (int mt = 0; mt < 4; mt++)
#pragma unroll
                for (int nt = 0; nt < 4; nt++)
                    mma_tf32(acc[mt][nt], a[mt], b[nt]);
        }
        __syncthreads();
        if (s + 2 < K / 32) issue((s + 2) * 32, s & 1);
    }

#pragma unroll
    for (int mt = 0; mt < 4; mt++)
#pragma unroll
        for (int nt = 0; nt < 4; nt++)
#pragma unroll
            for (int c = 0; c < 4; c++) {
                int m = m0 + wm * 64 + mt * 16 + gid + 8 * (c >> 1);
                int n = n0 + wn * 32 + nt * 8 + tig * 2 + (c & 1);
                epi(m, n, acc[mt][nt][c]);
            }
}

struct QkvEpilogue {
    const float* bias;
    float* kout;
    float* vout;
    __device__ __forceinline__ void operator()(int m, int n, float v) const {
        v += bias[n];
        int bidx = m >> 11;
        int t    = m & 2047;
        int s = n >> 10;
        int cc = n & 1023;
        int h = cc >> 6, d = cc & 63;
        int idx = ((bidx * kH + h) * kT + t) * kHD + d;
        if (s == 0)      g_q[idx]  = v;
        else if (s == 1) kout[idx] = v;
        else             vout[idx] = v;
    }
};

__global__ void __launch_bounds__(256, 2) qkv_gemm_kernel(
    const float* __restrict__ bias,
    float* __restrict__ kout, float* __restrict__ vout)
{
    QkvEpilogue epi{bias, kout, vout};
    gemm_tf32_core<3 * kC>(g_xc, g_wc, epi);
}

struct ProjEpilogue {
    const float* bias;
    float* out;
    __device__ __forceinline__ void operator()(int m, int n, float v) const {
        out[(size_t)m * kC + n] = v + bias[n];
    }
};

__global__ void __launch_bounds__(256, 2) proj_gemm_kernel(
    const float* __restrict__ bias, float* __restrict__ out)
{
    ProjEpilogue epi{bias, out};
    gemm_tf32_core<kC>(g_yatt, g_wp, epi);
}

// ---------------------------------------------------------------------------
// TF32 MMA flash attention v2. BR=128, BC=64. 256 threads = 8 warps; warp w
// owns q-rows [w*16, w*16+16) => softmax stays warp-local; K/V staging cost
// per unit MMA work is HALVED vs BR=64.
// Smem: Ss[128][68] (Q stage + P round-trip), Ks[64][68], Vt[64][68] = 68KB.
// qi reversed so heaviest CTAs launch first.
// ---------------------------------------------------------------------------
constexpr int kFlashSmemBytes = (128 + 64 + 64) * 68 * 4;   // 69632

__global__ void __launch_bounds__(256, 2) flash_kernel(
    const float* __restrict__ Kg, const float* __restrict__ Vg)
{
    extern __shared__ float sm[];
    float* Ss = sm;                 // [128][68]
    float* Ks = sm + 128 * 68;      // [64][68]
    float* Vt = sm + 192 * 68;      // [64][68]  (Vt[d][c])

    const int tid  = threadIdx.x;
    const int lane = tid & 31;
    const int wid  = tid >> 5;
    const int gid  = lane >> 2;
    const int tig  = lane & 3;
    const int qi = (gridDim.x - 1) - blockIdx.x;   // heavy CTAs first
    const int h = blockIdx.y, b = blockIdx.z;
    const int qbase = qi * 128;
    const int r0 = wid * 16;

    const size_t head_off = (size_t)(b * kH + h) * kT * kHD;
    const float* Qp = g_q + head_off;
    const float* Kp = Kg + head_off;
    const float* Vp = Vg + head_off;

    // ---- stage Q tile (128x64) into Ss, then load fragments (scaled, tf32) ----
#pragma unroll
    for (int it = 0; it < 8; it++) {
        int f = it * 256 + tid;
        int r = f >> 4, dq = (f & 15) * 4;
        float4 q4 = *reinterpret_cast<const float4*>(Qp + (size_t)(qbase + r) * kHD + dq);
        float* d = Ss + r * 68 + dq;
        d[0] = q4.x; d[1] = q4.y; d[2] = q4.z; d[3] = q4.w;
    }
    __syncthreads();

    uint32_t qf[8][4];
#pragma unroll
    for (int kc = 0; kc < 8; kc++) {
        const float* base = Ss + (r0 + gid) * 68 + kc * 8 + tig;
        qf[kc][0] = __float_as_uint(to_tf32(0.125f * base[0]));
        qf[kc][1] = __float_as_uint(to_tf32(0.125f * base[8 * 68]));
        qf[kc][2] = __float_as_uint(to_tf32(0.125f * base[4]));
        qf[kc][3] = __float_as_uint(to_tf32(0.125f * base[8 * 68 + 4]));
    }

    float mA = -INFINITY, mB = -INFINITY, lA = 0.f, lB = 0.f;
    float oacc[8][4];
#pragma unroll
    for (int nt = 0; nt < 8; nt++)
#pragma unroll
        for (int c = 0; c < 4; c++) oacc[nt][c] = 0.f;

    const int ntiles = 2 * qi + 2;
    const int vdpb = tid & 15, vcb = tid >> 4;     // V transpose block coords

    for (int jt = 0; jt < ntiles; jt++) {
        __syncthreads();
        // ---- stage K tile row-major (tf32): 64x64 ----
#pragma unroll
        for (int it = 0; it < 4; it++) {
            int f = it * 256 + tid;
            int r = f >> 4, dq = (f & 15) * 4;
            float4 k4 = *reinterpret_cast<const float4*>(Kp + (size_t)(jt * 64 + r) * kHD + dq);
            float* d = Ks + r * 68 + dq;
            d[0] = to_tf32(k4.x); d[1] = to_tf32(k4.y);
            d[2] = to_tf32(k4.z); d[3] = to_tf32(k4.w);
        }
        // ---- stage V transposed via 4x4 in-register blocks (tf32) ----
        {
            const float* vsrc = Vp + (size_t)(jt * 64 + vcb * 4) * kHD + vdpb * 4;
            float4 a0 = *reinterpret_cast<const float4*>(vsrc);
            float4 a1 = *reinterpret_cast<const float4*>(vsrc + kHD);
            float4 a2 = *reinterpret_cast<const float4*>(vsrc + 2 * kHD);
            float4 a3 = *reinterpret_cast<const float4*>(vsrc + 3 * kHD);
            float4 t0 = {to_tf32(a0.x), to_tf32(a1.x), to_tf32(a2.x), to_tf32(a3.x)};
            float4 t1 = {to_tf32(a0.y), to_tf32(a1.y), to_tf32(a2.y), to_tf32(a3.y)};
            float4 t2 = {to_tf32(a0.z), to_tf32(a1.z), to_tf32(a2.z), to_tf32(a3.z)};
            float4 t3 = {to_tf32(a0.w), to_tf32(a1.w), to_tf32(a2.w), to_tf32(a3.w)};
            *reinterpret_cast<float4*>(Vt + (vdpb * 4 + 0) * 68 + vcb * 4) = t0;
            *reinterpret_cast<float4*>(Vt + (vdpb * 4 + 1) * 68 + vcb * 4) = t1;
            *reinterpret_cast<float4*>(Vt + (vdpb * 4 + 2) * 68 + vcb * 4) = t2;
            *reinterpret_cast<float4*>(Vt + (vdpb * 4 + 3) * 68 + vcb * 4) = t3;
        }
        __syncthreads();

        // ---- S = (Q/8) K^T : 8 n-tiles x 8 k-chunks ----
        float sa[8][4];
#pragma unroll
        for (int nt = 0; nt < 8; nt++)
#pragma unroll
            for (int c = 0; c < 4; c++) sa[nt][c] = 0.f;
#pragma unroll
        for (int kc = 0; kc < 8; kc++) {
#pragma unroll
            for (int nt = 0; nt < 8; nt++) {
                const float* bp = Ks + (nt * 8 + gid) * 68 + kc * 8 + tig;
                uint32_t bb[2];
                bb[0] = __float_as_uint(bp[0]);
                bb[1] = __float_as_uint(bp[4]);
                mma_tf32(sa[nt], qf[kc], bb);
            }
        }

        // ---- causal mask (per-warp: fires on diagonal-region tiles) ----
        if (jt * 64 + 63 > qbase + r0) {
            int rA = qbase + r0 + gid - jt * 64;    // local row coords
            int rB = rA + 8;
#pragma unroll
            for (int nt = 0; nt < 8; nt++) {
                int c0 = nt * 8 + tig * 2, c1 = c0 + 1;
                if (c0 > rA) sa[nt][0] = -INFINITY;
                if (c1 > rA) sa[nt][1] = -INFINITY;
                if (c0 > rB) sa[nt][2] = -INFINITY;
                if (c1 > rB) sa[nt][3] = -INFINITY;
            }
        }

        // ---- warp-local online softmax ----
        float mxA = -INFINITY, mxB = -INFINITY;
#pragma unroll
        for (int nt = 0; nt < 8; nt++) {
            mxA = fmaxf(mxA, fmaxf(sa[nt][0], sa[nt][1]));
            mxB = fmaxf(mxB, fmaxf(sa[nt][2], sa[nt][3]));
        }
        mxA = fmaxf(mxA, __shfl_xor_sync(0xffffffff, mxA, 1));
        mxA = fmaxf(mxA, __shfl_xor_sync(0xffffffff, mxA, 2));
        mxB = fmaxf(mxB, __shfl_xor_sync(0xffffffff, mxB, 1));
        mxB = fmaxf(mxB, __shfl_xor_sync(0xffffffff, mxB, 2));

        float mnA = fmaxf(mA, mxA), mnB = fmaxf(mB, mxB);
        float alphaA = __expf(mA - mnA), alphaB = __expf(mB - mnB);

        float sumA = 0.f, sumB = 0.f;
        float* prowA = Ss + (r0 + gid) * 68 + tig * 2;
        float* prowB = prowA + 8 * 68;
#pragma unroll
        for (int nt = 0; nt < 8; nt++) {
            float p0 = __expf(sa[nt][0] - mnA);
            float p1 = __expf(sa[nt][1] - mnA);
            float p2 = __expf(sa[nt][2] - mnB);
            float p3 = __expf(sa[nt][3] - mnB);
            float q0 = to_tf32(p0), q1 = to_tf32(p1);
            float q2 = to_tf32(p2), q3 = to_tf32(p3);
            sumA += q0 + q1;
            sumB += q2 + q3;
            prowA[nt * 8 + 0] = q0; prowA[nt * 8 + 1] = q1;
            prowB[nt * 8 + 0] = q2; prowB[nt * 8 + 1] = q3;
        }
        sumA += __shfl_xor_sync(0xffffffff, sumA, 1);
        sumA += __shfl_xor_sync(0xffffffff, sumA, 2);
        sumB += __shfl_xor_sync(0xffffffff, sumB, 1);
        sumB += __shfl_xor_sync(0xffffffff, sumB, 2);

        lA = lA * alphaA + sumA;  mA = mnA;
        lB = lB * alphaB + sumB;  mB = mnB;

#pragma unroll
        for (int nt = 0; nt < 8; nt++) {
            oacc[nt][0] *= alphaA; oacc[nt][1] *= alphaA;
            oacc[nt][2] *= alphaB; oacc[nt][3] *= alphaB;
        }
        __syncwarp();

        // ---- O += P V ----
#pragma unroll
        for (int kc = 0; kc < 8; kc++) {
            const float* ap = Ss + (r0 + gid) * 68 + kc * 8 + tig;
            uint32_t pa[4];
            pa[0] = __float_as_uint(ap[0]);
            pa[1] = __float_as_uint(ap[8 * 68]);
            pa[2] = __float_as_uint(ap[4]);
            pa[3] = __float_as_uint(ap[8 * 68 + 4]);
#pragma unroll
            for (int nt = 0; nt < 8; nt++) {
                const float* bp = Vt + (nt * 8 + gid) * 68 + kc * 8 + tig;
                uint32_t bb[2];
                bb[0] = __float_as_uint(bp[0]);
                bb[1] = __float_as_uint(bp[4]);
                mma_tf32(oacc[nt], pa, bb);
            }
        }
        __syncwarp();
    }

    // Output is tf32-rounded so proj can consume it without converting.
    float ilA = 1.f / lA, ilB = 1.f / lB;
    float* ypA = g_yatt + ((size_t)(b * kT + qbase + r0 + gid)) * kC + h * kHD;
    float* ypB = ypA + (size_t)8 * kC;
#pragma unroll
    for (int nt = 0; nt < 8; nt++) {
        float2 vA = {to_tf32(oacc[nt][0] * ilA), to_tf32(oacc[nt][1] * ilA)};
        float2 vB = {to_tf32(oacc[nt][2] * ilB), to_tf32(oacc[nt][3] * ilB)};
        *reinterpret_cast<float2*>(ypA + nt * 8 + tig * 2) = vA;
        *reinterpret_cast<float2*>(ypB + nt * 8 + tig * 2) = vB;
    }
}

// ---------------------------------------------------------------------------
// Launch: cvt -> qkv -> flash -> proj, sequential default stream (capturable).
// Output layout: [ y (B*T*C) | k (B*H*T*hd) | v (B*H*T*hd) ]
// ---------------------------------------------------------------------------
extern "C" void kernel_launch(void* const* d_in, const int* in_sizes, int n_in,
                              void* d_out, int out_size)
{
    const float* x      = (const float*)d_in[0];
    const float* W_attn = (const float*)d_in[1];
    const float* b_attn = (const float*)d_in[2];
    const float* W_proj = (const float*)d_in[3];
    const float* b_proj = (const float*)d_in[4];

    float* y = (float*)d_out;
    const int seg = out_size / 3;       // 4,194,304 each
    float* kout = y + seg;
    float* vout = y + 2 * seg;

    cudaFuncSetAttribute(qkv_gemm_kernel,
                         cudaFuncAttributeMaxDynamicSharedMemorySize, kGemmSmemBytes);
    cudaFuncSetAttribute(proj_gemm_kernel,
                         cudaFuncAttributeMaxDynamicSharedMemorySize, kGemmSmemBytes);
    cudaFuncSetAttribute(flash_kernel,
                         cudaFuncAttributeMaxDynamicSharedMemorySize, kFlashSmemBytes);

    cvt_tf32_kernel<<<kCvtTotal4 / 256, 256>>>(x, W_attn, W_proj);
    // QKV: M=4096 -> 32 m-tiles, N=3072 -> 24 n-tiles
    qkv_gemm_kernel<<<dim3(24, 32), 256, kGemmSmemBytes>>>(b_attn, kout, vout);
    // Attention: (T/128, H, B) = (16, 16, 2)
    flash_kernel<<<dim3(16, 16, 2), 256, kFlashSmemBytes>>>(kout, vout);
    // Proj: N=1024 -> 8 n-tiles
    proj_gemm_kernel<<<dim3(8, 32), 256, kGemmSmemBytes>>>(b_proj, y);
}

// round 15
// speedup vs baseline: 1.0311x; 1.0156x over previous
#include <cuda_runtime.h>
#include <math.h>
#include <stdint.h>

// Problem constants: B=2, T=2048, C=1024, H=16, hd=64
constexpr int kT  = 2048;
constexpr int kC  = 1024;
constexpr int kH  = 16;
constexpr int kHD = 64;
constexpr int kB  = 2;

// Scratch (allocation-free rule: __device__ globals)
__device__ float g_q[kB * kH * kT * kHD];     // Q in [B,H,T,hd]        (16 MB)
__device__ float g_yatt[kB * kT * kC];        // attn out (tf32-rounded) (16 MB)
__device__ float g_xc[kB * kT * kC];          // x, tf32-rounded         (16 MB)
__device__ float g_wc[kC * 3 * kC];           // W_attn, tf32-rounded    (12 MB)
__device__ float g_wp[kC * kC];               // W_proj, tf32-rounded    ( 4 MB)

// ---------------------------------------------------------------------------
// TF32 + cp.async helpers
// ---------------------------------------------------------------------------
__device__ __forceinline__ float to_tf32(float x) {
    float r;
    asm("cvt.rna.tf32.f32 %0, %1;" : "=f"(r) : "f"(x));
    return r;
}

__device__ __forceinline__ void mma_tf32(float* c, const uint32_t* a, const uint32_t* b) {
    asm volatile(
        "mma.sync.aligned.m16n8k8.row.col.f32.tf32.tf32.f32 "
        "{%0,%1,%2,%3}, {%4,%5,%6,%7}, {%8,%9}, {%0,%1,%2,%3};\n"
        : "+f"(c[0]), "+f"(c[1]), "+f"(c[2]), "+f"(c[3])
        : "r"(a[0]), "r"(a[1]), "r"(a[2]), "r"(a[3]), "r"(b[0]), "r"(b[1]));
}

__device__ __forceinline__ uint32_t smem_u32(const void* p) {
    uint32_t a;
    asm("{ .reg .u64 t; cvta.to.shared.u64 t, %1; cvt.u32.u64 %0, t; }"
        : "=r"(a) : "l"(p));
    return a;
}

#define CP_ASYNC16(saddr, gptr) \
    asm volatile("cp.async.cg.shared.global [%0], [%1], 16;" \
                 :: "r"(saddr), "l"(gptr) : "memory")
#define CP_COMMIT() asm volatile("cp.async.commit_group;" ::: "memory")
#define CP_WAIT1()  asm volatile("cp.async.wait_group 1;" ::: "memory")
#define CP_WAIT0()  asm volatile("cp.async.wait_group 0;" ::: "memory")

// ---------------------------------------------------------------------------
// Pre-round inputs to tf32 (single RNA rounding; hot loops stay cvt-free).
// ---------------------------------------------------------------------------
constexpr int kX4  = kB * kT * kC / 4;        // 1048576
constexpr int kWA4 = kC * 3 * kC / 4;         //  786432
constexpr int kWP4 = kC * kC / 4;             //  262144
constexpr int kCvtTotal4 = kX4 + kWA4 + kWP4; // 2097152

__global__ void __launch_bounds__(256) cvt_tf32_kernel(
    const float* __restrict__ x, const float* __restrict__ wa,
    const float* __restrict__ wp)
{
    int i = blockIdx.x * blockDim.x + threadIdx.x;
    const float4* src;
    float4* dst;
    if (i < kX4) {
        src = reinterpret_cast<const float4*>(x) + i;
        dst = reinterpret_cast<float4*>(g_xc) + i;
    } else if (i < kX4 + kWA4) {
        src = reinterpret_cast<const float4*>(wa) + (i - kX4);
        dst = reinterpret_cast<float4*>(g_wc) + (i - kX4);
    } else {
        src = reinterpret_cast<const float4*>(wp) + (i - kX4 - kWA4);
        dst = reinterpret_cast<float4*>(g_wp) + (i - kX4 - kWA4);
    }
    float4 v = *src;
    float4 o = {to_tf32(v.x), to_tf32(v.y), to_tf32(v.z), to_tf32(v.w)};
    *dst = o;
}

// ---------------------------------------------------------------------------
// TF32 MMA GEMM v5. CTA 128x128, BK=32, 256 threads (8 warps: 2m x 4n),
// warp tile 64x32. 3-STAGE cp.async pipeline with ONE __syncthreads per slab:
// write target (s+2)%3 == (s-1)%3, whose readers are fenced by the
// top-of-iteration barrier; wait_group(1) ensures slab s has landed.
//   As[3][128][36]  (stride 36: frag bank = 4*gid+tig = lane, conflict-free)
//   Bs[3][32][136]  (stride 136: frag bank = 8*tig+gid, bijective, CF)
// Inputs must already be tf32-rounded (g_xc/g_wc/g_wp/g_yatt).
// ---------------------------------------------------------------------------
constexpr int kAStrideF = 36;   // floats; 144 B/row
constexpr int kBStrideF = 136;  // floats; 544 B/row
constexpr int kABufF = 128 * kAStrideF;   // 4608 floats = 18432 B
constexpr int kBBufF = 32 * kBStrideF;    // 4352 floats = 17408 B
constexpr int kGemmSmemBytes = 3 * (kABufF + kBBufF) * 4;  // 107520

template <int N_, typename Epilogue>
__device__ __forceinline__ void gemm_tf32_core(
    const float* __restrict__ A, const float* __restrict__ W,
    Epilogue epi)
{
    constexpr int K = kC;            // 1024
    constexpr int NSLAB = K / 32;    // 32
    extern __shared__ float smf[];
    float* As = smf;                    // [3][4608]
    float* Bs = smf + 3 * kABufF;       // [3][4352]

    const int m0 = blockIdx.y * 128;
    const int n0 = blockIdx.x * 128;
    const int tid  = threadIdx.x;
    const int lane = tid & 31;
    const int wid  = tid >> 5;
    const int wm = wid >> 2;      // 0..1
    const int wn = wid & 3;       // 0..3
    const int gid = lane >> 2, tig = lane & 3;

    const uint32_t aBase = smem_u32(As);
    const uint32_t bBase = smem_u32(Bs);

    // A: 4 chunks of 16B: row = it*32 + (tid>>3), k-chunk = (tid&7)
    const int aRow = tid >> 3;
    const int aC16 = tid & 7;
    const float* aG[4];
    uint32_t aS[4];
#pragma unroll
    for (int it = 0; it < 4; it++) {
        aG[it] = A + (size_t)(m0 + it * 32 + aRow) * K + aC16 * 4;
        aS[it] = (uint32_t)((it * 32 + aRow) * 144 + aC16 * 16);
    }
    // B: 4 chunks: k-row = it*8 + (tid>>5), n-chunk = (tid&31)
    const int bRow = tid >> 5;
    const int bC16 = tid & 31;
    const float* bG[4];
    uint32_t bS[4];
#pragma unroll
    for (int it = 0; it < 4; it++) {
        bG[it] = W + (size_t)(it * 8 + bRow) * N_ + n0 + bC16 * 4;
        bS[it] = (uint32_t)((it * 8 + bRow) * 544 + bC16 * 16);
    }

    auto issue = [&](int k0, int buf) {
        uint32_t ab = aBase + buf * (kABufF * 4);
        uint32_t bb = bBase + buf * (kBBufF * 4);
#pragma unroll
        for (int it = 0; it < 4; it++)
            CP_ASYNC16(ab + aS[it], aG[it] + k0);
        size_t wof = (size_t)k0 * N_;
#pragma unroll
        for (int it = 0; it < 4; it++)
            CP_ASYNC16(bb + bS[it], bG[it] + wof);
        CP_COMMIT();
    };

    float acc[4][4][4];
#pragma unroll
    for (int i = 0; i < 4; i++)
#pragma unroll
        for (int j = 0; j < 4; j++)
#pragma unroll
            for (int c = 0; c < 4; c++) acc[i][j][c] = 0.f;

    issue(0, 0);
    issue(32, 1);

    const int arow0 = wm * 64 + gid;
    const int nb0   = wn * 32 + gid;

    int bufR = 0;          // s % 3
    int bufW = 2;          // (s+2) % 3
    for (int s = 0; s < NSLAB; s++) {
        if (s == NSLAB - 1) { CP_WAIT0(); } else { CP_WAIT1(); }
        __syncthreads();
        if (s + 2 < NSLAB) issue((s + 2) * 32, bufW);

        const float* ab = As + bufR * kABufF;
        const float* bb = Bs + bufR * kBBufF;
#pragma unroll
        for (int kc = 0; kc < 4; kc++) {
            const int kcol = kc * 8 + tig;
            uint32_t a[4][4], b[4][2];
#pragma unroll
            for (int mt = 0; mt < 4; mt++) {
                const float* p = ab + (arow0 + mt * 16) * kAStrideF + kcol;
                a[mt][0] = __float_as_uint(p[0]);
                a[mt][1] = __float_as_uint(p[8 * kAStrideF]);
                a[mt][2] = __float_as_uint(p[4]);
                a[mt][3] = __float_as_uint(p[8 * kAStrideF + 4]);
            }
#pragma unroll
            for (int nt = 0; nt < 4; nt++) {
                const float* q = bb + kcol * kBStrideF + nb0 + nt * 8;
                b[nt][0] = __float_as_uint(q[0]);
                b[nt][1] = __float_as_uint(q[4 * kBStrideF]);
            }
#pragma unroll
            for (int mt = 0; mt < 4; mt++)
#pragma unroll
                for (int nt = 0; nt < 4; nt++)
                    mma_tf32(acc[mt][nt], a[mt], b[nt]);
        }
        bufR = (bufR == 2) ? 0 : bufR + 1;
        bufW = (bufW == 2) ? 0 : bufW + 1;
    }

#pragma unroll
    for (int mt = 0; mt < 4; mt++)
#pragma unroll
        for (int nt = 0; nt < 4; nt++)
#pragma unroll
            for (int c = 0; c < 4; c++) {
                int m = m0 + wm * 64 + mt * 16 + gid + 8 * (c >> 1);
                int n = n0 + wn * 32 + nt * 8 + tig * 2 + (c & 1);
                epi(m, n, acc[mt][nt][c]);
            }
}

struct QkvEpilogue {
    const float* bias;
    float* kout;
    float* vout;
    __device__ __forceinline__ void operator()(int m, int n, float v) const {
        v += bias[n];
        int bidx = m >> 11;
        int t    = m & 2047;
        int s = n >> 10;
        int cc = n & 1023;
        int h = cc >> 6, d = cc & 63;
        int idx = ((bidx * kH + h) * kT + t) * kHD + d;
        if (s == 0)      g_q[idx]  = v;
        else if (s == 1) kout[idx] = v;
        else             vout[idx] = v;
    }
};

__global__ void __launch_bounds__(256, 2) qkv_gemm_kernel(
    const float* __restrict__ bias,
    float* __restrict__ kout, float* __restrict__ vout)
{
    QkvEpilogue epi{bias, kout, vout};
    gemm_tf32_core<3 * kC>(g_xc, g_wc, epi);
}

struct ProjEpilogue {
    const float* bias;
    float* out;
    __device__ __forceinline__ void operator()(int m, int n, float v) const {
        out[(size_t)m * kC + n] = v + bias[n];
    }
};

__global__ void __launch_bounds__(256, 2) proj_gemm_kernel(
    const float* __restrict__ bias, float* __restrict__ out)
{
    ProjEpilogue epi{bias, out};
    gemm_tf32_core<kC>(g_yatt, g_wp, epi);
}

// ---------------------------------------------------------------------------
// TF32 MMA flash attention (R10 core — measured best). BR=BC=64, 128 threads
// = 4 warps; warp-local softmax. qi reversed: heaviest CTAs launch first.
// Smem: Ks[64][68], Vt[64][68], Ss[64][68] = 52224 B.
// ---------------------------------------------------------------------------
constexpr int kFlashSmemBytes = 3 * 64 * 68 * 4;

__global__ void __launch_bounds__(128) flash_kernel(
    const float* __restrict__ Kg, const float* __restrict__ Vg)
{
    extern __shared__ float sm[];
    float* Ks = sm;               // [64][68]
    float* Vt = sm + 64 * 68;     // [64][68]  (Vt[d][c])
    float* Ss = sm + 2 * 64 * 68; // [64][68]

    const int tid  = threadIdx.x;
    const int lane = tid & 31;
    const int wid  = tid >> 5;
    const int gid  = lane >> 2;
    const int tig  = lane & 3;
    const int qi = (gridDim.x - 1) - blockIdx.x;   // heavy CTAs first
    const int h = blockIdx.y, b = blockIdx.z;
    const int qbase = qi * 64;
    const int r0 = wid * 16;

    const size_t head_off = (size_t)(b * kH + h) * kT * kHD;
    const float* Qp = g_q + head_off;
    const float* Kp = Kg + head_off;
    const float* Vp = Vg + head_off;

#pragma unroll
    for (int it = 0; it < 8; it++) {
        int f = it * 128 + tid;
        int r = f >> 4, dq = (f & 15) * 4;
        float4 q4 = *reinterpret_cast<const float4*>(Qp + (size_t)(qbase + r) * kHD + dq);
        float* d = Ss + r * 68 + dq;
        d[0] = q4.x; d[1] = q4.y; d[2] = q4.z; d[3] = q4.w;
    }
    __syncthreads();

    uint32_t qf[8][4];
#pragma unroll
    for (int kc = 0; kc < 8; kc++) {
        const float* base = Ss + (r0 + gid) * 68 + kc * 8 + tig;
        qf[kc][0] = __float_as_uint(to_tf32(0.125f * base[0]));
        qf[kc][1] = __float_as_uint(to_tf32(0.125f * base[8 * 68]));
        qf[kc][2] = __float_as_uint(to_tf32(0.125f * base[4]));
        qf[kc][3] = __float_as_uint(to_tf32(0.125f * base[8 * 68 + 4]));
    }

    float mA = -INFINITY, mB = -INFINITY, lA = 0.f, lB = 0.f;
    float oacc[8][4];
#pragma unroll
    for (int nt = 0; nt < 8; nt++)
#pragma unroll
        for (int c = 0; c < 4; c++) oacc[nt][c] = 0.f;

    const int ntiles = qi + 1;
    const int vdpb = tid & 15, vcb4 = tid >> 4;

    for (int jt = 0; jt < ntiles; jt++) {
        __syncthreads();
#pragma unroll
        for (int it = 0; it < 8; it++) {
            int f = it * 128 + tid;
            int r = f >> 4, dq = (f & 15) * 4;
            float4 k4 = *reinterpret_cast<const float4*>(Kp + (size_t)(jt * 64 + r) * kHD + dq);
            float* d = Ks + r * 68 + dq;
            d[0] = to_tf32(k4.x); d[1] = to_tf32(k4.y);
            d[2] = to_tf32(k4.z); d[3] = to_tf32(k4.w);
        }
#pragma unroll
        for (int it = 0; it < 2; it++) {
            int cb = vcb4 + 8 * it;
            const float* vsrc = Vp + (size_t)(jt * 64 + cb * 4) * kHD + vdpb * 4;
            float4 a0 = *reinterpret_cast<const float4*>(vsrc);
            float4 a1 = *reinterpret_cast<const float4*>(vsrc + kHD);
            float4 a2 = *reinterpret_cast<const float4*>(vsrc + 2 * kHD);
            float4 a3 = *reinterpret_cast<const float4*>(vsrc + 3 * kHD);
            float4 t0 = {to_tf32(a0.x), to_tf32(a1.x), to_tf32(a2.x), to_tf32(a3.x)};
            float4 t1 = {to_tf32(a0.y), to_tf32(a1.y), to_tf32(a2.y), to_tf32(a3.y)};
            float4 t2 = {to_tf32(a0.z), to_tf32(a1.z), to_tf32(a2.z), to_tf32(a3.z)};
            float4 t3 = {to_tf32(a0.w), to_tf32(a1.w), to_tf32(a2.w), to_tf32(a3.w)};
            *reinterpret_cast<float4*>(Vt + (vdpb * 4 + 0) * 68 + cb * 4) = t0;
            *reinterpret_cast<float4*>(Vt + (vdpb * 4 + 1) * 68 + cb * 4) = t1;
            *reinterpret_cast<float4*>(Vt + (vdpb * 4 + 2) * 68 + cb * 4) = t2;
            *reinterpret_cast<float4*>(Vt + (vdpb * 4 + 3) * 68 + cb * 4) = t3;
        }
        __syncthreads();

        float sa[8][4];
#pragma unroll
        for (int nt = 0; nt < 8; nt++)
#pragma unroll
            for (int c = 0; c < 4; c++) sa[nt][c] = 0.f;
#pragma unroll
        for (int kc = 0; kc < 8; kc++) {
#pragma unroll
            for (int nt = 0; nt < 8; nt++) {
                const float* bp = Ks + (nt * 8 + gid) * 68 + kc * 8 + tig;
                uint32_t bb[2];
                bb[0] = __float_as_uint(bp[0]);
                bb[1] = __float_as_uint(bp[4]);
                mma_tf32(sa[nt], qf[kc], bb);
            }
        }

        if (jt == ntiles - 1) {
            int rowA = r0 + gid, rowB = rowA + 8;
#pragma unroll
            for (int nt = 0; nt < 8; nt++) {
                int c0 = nt * 8 + tig * 2, c1 = c0 + 1;
                if (c0 > rowA) sa[nt][0] = -INFINITY;
                if (c1 > rowA) sa[nt][1] = -INFINITY;
                if (c0 > rowB) sa[nt][2] = -INFINITY;
                if (c1 > rowB) sa[nt][3] = -INFINITY;
            }
        }

        float mxA = -INFINITY, mxB = -INFINITY;
#pragma unroll
        for (int nt = 0; nt < 8; nt++) {
            mxA = fmaxf(mxA, fmaxf(sa[nt][0], sa[nt][1]));
            mxB = fmaxf(mxB, fmaxf(sa[nt][2], sa[nt][3]));
        }
        mxA = fmaxf(mxA, __shfl_xor_sync(0xffffffff, mxA, 1));
        mxA = fmaxf(mxA, __shfl_xor_sync(0xffffffff, mxA, 2));
        mxB = fmaxf(mxB, __shfl_xor_sync(0xffffffff, mxB, 1));
        mxB = fmaxf(mxB, __shfl_xor_sync(0xffffffff, mxB, 2));

        float mnA = fmaxf(mA, mxA), mnB = fmaxf(mB, mxB);
        float alphaA = __expf(mA - mnA), alphaB = __expf(mB - mnB);

        float sumA = 0.f, sumB = 0.f;
        float* prowA = Ss + (r0 + gid) * 68 + tig * 2;
        float* prowB = prowA + 8 * 68;
#pragma unroll
        for (int nt = 0; nt < 8; nt++) {
            float p0 = __expf(sa[nt][0] - mnA);
            float p1 = __expf(sa[nt][1] - mnA);
            float p2 = __expf(sa[nt][2] - mnB);
            float p3 = __expf(sa[nt][3] - mnB);
            float q0 = to_tf32(p0), q1 = to_tf32(p1);
            float q2 = to_tf32(p2), q3 = to_tf32(p3);
            sumA += q0 + q1;
            sumB += q2 + q3;
            prowA[nt * 8 + 0] = q0; prowA[nt * 8 + 1] = q1;
            prowB[nt * 8 + 0] = q2; prowB[nt * 8 + 1] = q3;
        }
        sumA += __shfl_xor_sync(0xffffffff, sumA, 1);
        sumA += __shfl_xor_sync(0xffffffff, sumA, 2);
        sumB += __shfl_xor_sync(0xffffffff, sumB, 1);
        sumB += __shfl_xor_sync(0xffffffff, sumB, 2);

        lA = lA * alphaA + sumA;  mA = mnA;
        lB = lB * alphaB + sumB;  mB = mnB;

#pragma unroll
        for (int nt = 0; nt < 8; nt++) {
            oacc[nt][0] *= alphaA; oacc[nt][1] *= alphaA;
            oacc[nt][2] *= alphaB; oacc[nt][3] *= alphaB;
        }
        __syncwarp();

#pragma unroll
        for (int kc = 0; kc < 8; kc++) {
            const float* ap = Ss + (r0 + gid) * 68 + kc * 8 + tig;
            uint32_t pa[4];
            pa[0] = __float_as_uint(ap[0]);
            pa[1] = __float_as_uint(ap[8 * 68]);
            pa[2] = __float_as_uint(ap[4]);
            pa[3] = __float_as_uint(ap[8 * 68 + 4]);
#pragma unroll
            for (int nt = 0; nt < 8; nt++) {
                const float* bp = Vt + (nt * 8 + gid) * 68 + kc * 8 + tig;
                uint32_t bb[2];
                bb[0] = __float_as_uint(bp[0]);
                bb[1] = __float_as_uint(bp[4]);
                mma_tf32(oacc[nt], pa, bb);
            }
        }
        __syncwarp();
    }

    // Output is tf32-rounded so proj can consume it without converting.
    float ilA = 1.f / lA, ilB = 1.f / lB;
    float* ypA = g_yatt + ((size_t)(b * kT + qbase + r0 + gid)) * kC + h * kHD;
    float* ypB = ypA + (size_t)8 * kC;
#pragma unroll
    for (int nt = 0; nt < 8; nt++) {
        float2 vA = {to_tf32(oacc[nt][0] * ilA), to_tf32(oacc[nt][1] * ilA)};
        float2 vB = {to_tf32(oacc[nt][2] * ilB), to_tf32(oacc[nt][3] * ilB)};
        *reinterpret_cast<float2*>(ypA + nt * 8 + tig * 2) = vA;
        *reinterpret_cast<float2*>(ypB + nt * 8 + tig * 2) = vB;
    }
}

// ---------------------------------------------------------------------------
// Launch: cvt -> qkv -> flash -> proj, sequential default stream (capturable).
// Output layout: [ y (B*T*C) | k (B*H*T*hd) | v (B*H*T*hd) ]
// ---------------------------------------------------------------------------
extern "C" void kernel_launch(void* const* d_in, const int* in_sizes, int n_in,
                              void* d_out, int out_size)
{
    const float* x      = (const float*)d_in[0];
    const float* W_attn = (const float*)d_in[1];
    const float* b_attn = (const float*)d_in[2];
    const float* W_proj = (const float*)d_in[3];
    const float* b_proj = (const float*)d_in[4];

    float* y = (float*)d_out;
    const int seg = out_size / 3;       // 4,194,304 each
    float* kout = y + seg;
    float* vout = y + 2 * seg;

    cudaFuncSetAttribute(qkv_gemm_kernel,
                         cudaFuncAttributeMaxDynamicSharedMemorySize, kGemmSmemBytes);
    cudaFuncSetAttribute(proj_gemm_kernel,
                         cudaFuncAttributeMaxDynamicSharedMemorySize, kGemmSmemBytes);
    cudaFuncSetAttribute(flash_kernel,
                         cudaFuncAttributeMaxDynamicSharedMemorySize, kFlashSmemBytes);

    cvt_tf32_kernel<<<kCvtTotal4 / 256, 256>>>(x, W_attn, W_proj);
    // QKV: M=4096 -> 32 m-tiles, N=3072 -> 24 n-tiles
    qkv_gemm_kernel<<<dim3(24, 32), 256, kGemmSmemBytes>>>(b_attn, kout, vout);
    // Attention: (T/64, H, B)
    flash_kernel<<<dim3(32, 16, 2), 128, kFlashSmemBytes>>>(kout, vout);
    // Proj: N=1024 -> 8 n-tiles
    proj_gemm_kernel<<<dim3(8, 32), 256, kGemmSmemBytes>>>(b_proj, y);
}